// round 13
// baseline (speedup 1.0000x reference)
#include <cuda_runtime.h>
#include <cuda_bf16.h>

#define FULL_MASK 0xffffffffu
#define EPW 128          // edges per warp-chunk (4 groups x 32 edges)
#define D   32           // feature dim (fixed by problem shape)

// Scratch (no cudaMalloc allowed). Zero-initialized at module load; k_fin
// restores zeros after consuming, so every kernel_launch call (correctness
// run + each graph replay) sees zeros. No static guards, fully deterministic.
__device__ float4 g_sums4[1 << 20];   // 16 MB: N*8 quads, N <= 131072
__device__ float  g_counts[1 << 17];  // per-segment edge counts

// ---------------------------------------------------------------------------
// 128-bit reduction (fire-and-forget) — sm_90+ vector atomic
// ---------------------------------------------------------------------------
__device__ __forceinline__ void red_add_v4(float4* p, float4 s) {
    asm volatile("red.global.add.v4.f32 [%0], {%1, %2, %3, %4};"
                 :: "l"(p), "f"(s.x), "f"(s.y), "f"(s.z), "f"(s.w)
                 : "memory");
}

// flush: one REDG.128 for the run's raw sum; group leader also counts.
__device__ __forceinline__ void flush_seg(int seg, float4 s, int cnt, int sub) {
    red_add_v4(&g_sums4[seg * 8 + sub], s);
    if (sub == 0) atomicAdd(&g_counts[seg], (float)cnt);
}

// ---------------------------------------------------------------------------
// Kernel 1: gather + sorted-segment raw sum + counts (round-12 engine).
// Warp = 4 groups of 8 lanes. Group g owns contiguous edges
// [start + g*32, start + g*32 + 32). Lane sub owns feature columns
// [sub*4, sub*4+4) as a float4. Phase 1 issues 8 independent LDG.128 row
// reads (MLP=8/lane); phase 2 run-length accumulates, flushing on segment
// change. Nothing else inside the loops.
// ---------------------------------------------------------------------------
__global__ void __launch_bounds__(256)
k_agg(const float* __restrict__ src,
      const int*   __restrict__ gidx,
      const int*   __restrict__ sid,
      int E)
{
    const int lane = threadIdx.x & 31;
    const int sub  = lane & 7;
    const long long warp  = ((long long)blockIdx.x * blockDim.x + threadIdx.x) >> 5;
    const long long start = warp * (long long)EPW;
    if (start >= E) return;

    if (start + EPW <= E) {
        // ---------- fast path: full 128-edge chunk ----------
        int4 gi4 = __ldg((const int4*)(gidx + start) + lane);
        int4 si4 = __ldg((const int4*)(sid  + start) + lane);
        int gi[4] = {gi4.x, gi4.y, gi4.z, gi4.w};
        int si[4] = {si4.x, si4.y, si4.z, si4.w};

        int    cur = -1, cnt = 0;
        float4 sum = make_float4(0.f, 0.f, 0.f, 0.f);

        #pragma unroll
        for (int jo = 0; jo < 32; jo += 8) {
            float4 val[8];
            #pragma unroll
            for (int jj = 0; jj < 8; ++jj) {
                const int j = jo + jj;
                int idx = __shfl_sync(FULL_MASK, gi[j & 3], j >> 2, 8);
                val[jj] = __ldg((const float4*)(src + (long long)idx * D) + sub);
            }
            #pragma unroll
            for (int jj = 0; jj < 8; ++jj) {
                const int j = jo + jj;
                int seg = __shfl_sync(FULL_MASK, si[j & 3], j >> 2, 8);
                if (seg != cur) {
                    if (cnt) flush_seg(cur, sum, cnt, sub);
                    cur = seg; sum = make_float4(0.f, 0.f, 0.f, 0.f); cnt = 0;
                }
                sum.x += val[jj].x; sum.y += val[jj].y;
                sum.z += val[jj].z; sum.w += val[jj].w;
                ++cnt;
            }
        }
        if (cnt) flush_seg(cur, sum, cnt, sub);
    } else {
        // ---------- tail path: partial chunk, per-group scalar loop ----------
        const int group = lane >> 3;
        long long gstart = start + (long long)group * 32;
        long long gend   = min(gstart + 32, (long long)E);

        int    cur = -1, cnt = 0;
        float4 sum = make_float4(0.f, 0.f, 0.f, 0.f);

        for (long long e = gstart; e < gend; ++e) {
            int idx = __ldg(gidx + e);
            int seg = __ldg(sid  + e);
            float4 v = __ldg((const float4*)(src + (long long)idx * D) + sub);
            if (seg != cur) {
                if (cnt) flush_seg(cur, sum, cnt, sub);
                cur = seg; sum = make_float4(0.f, 0.f, 0.f, 0.f); cnt = 0;
            }
            sum.x += v.x; sum.y += v.y; sum.z += v.z; sum.w += v.w;
            ++cnt;
        }
        if (cnt) flush_seg(cur, sum, cnt, sub);
    }
}

// ---------------------------------------------------------------------------
// Kernel 2: out = sums/max(cnt,1); restore scratch zeros. ILP-8.
// Thread t handles quads t, t+T, ..., t+7T (T = thread count): coalesced AND
// 8 independent load chains per thread (MLP=8). All data L2-hot.
// ---------------------------------------------------------------------------
__global__ void __launch_bounds__(256)
k_fin(float4* __restrict__ out4, int nq, int T)
{
    const int t = blockIdx.x * blockDim.x + threadIdx.x;
    if (t >= T) return;

    int    iv[8];
    float4 v[8];
    float  c[8];
    int    m = 0;

    #pragma unroll
    for (int k = 0; k < 8; ++k) {
        int i = t + k * T;
        if (i < nq) { iv[m] = i; v[m] = g_sums4[i]; c[m] = g_counts[i >> 3]; ++m; }
    }
    #pragma unroll
    for (int k = 0; k < 8; ++k) {
        if (k < m) {
            const int i = iv[k];
            const float inv = 1.0f / fmaxf(c[k], 1.0f);
            out4[i] = make_float4(v[k].x * inv, v[k].y * inv,
                                  v[k].z * inv, v[k].w * inv);
            g_sums4[i] = make_float4(0.f, 0.f, 0.f, 0.f);
            if ((i & 7) == 0) g_counts[i >> 3] = 0.0f;
        }
    }
}

// ---------------------------------------------------------------------------
extern "C" void kernel_launch(void* const* d_in, const int* in_sizes, int n_in,
                              void* d_out, int out_size)
{
    const float* src  = (const float*)d_in[0];   // [N, 32] f32
    const int*   gidx = (const int*)  d_in[1];   // [E] i32
    const int*   sid  = (const int*)  d_in[2];   // [E] i32 (sorted)
    float4*      out4 = (float4*)d_out;          // [N, 32] f32

    const int E  = in_sizes[1];
    const int nq = out_size / 4;

    // 1) gather + raw segment sums + counts into zeroed scratch
    {
        long long warps  = ((long long)E + EPW - 1) / EPW;
        long long tcount = warps * 32;
        int blocks = (int)((tcount + 255) / 256);
        k_agg<<<blocks, 256>>>(src, gidx, sid, E);
    }
    // 2) mean -> out, restore scratch zeros (ILP-8)
    {
        int T = (nq + 7) / 8;
        int blocks = (T + 255) / 256;
        k_fin<<<blocks, 256>>>(out4, nq, T);
    }
}

// round 14
// speedup vs baseline: 1.1161x; 1.1161x over previous
#include <cuda_runtime.h>
#include <cuda_bf16.h>

#define FULL_MASK 0xffffffffu
#define EPW 128          // edges per warp-chunk (4 groups x 32 edges)
#define D   32           // feature dim (fixed by problem shape)

// Scratch (no cudaMalloc allowed). Zero-initialized at module load; k_fin
// restores zeros after consuming, so every kernel_launch call (correctness
// run + each graph replay) sees zeros. No static guards, fully deterministic.
__device__ float4 g_sums4[1 << 20];   // 16 MB: N*8 quads, N <= 131072
__device__ float  g_counts[1 << 17];  // per-segment edge counts

// ---------------------------------------------------------------------------
// 128-bit reduction (fire-and-forget) — sm_90+ vector atomic
// ---------------------------------------------------------------------------
__device__ __forceinline__ void red_add_v4(float4* p, float4 s) {
    asm volatile("red.global.add.v4.f32 [%0], {%1, %2, %3, %4};"
                 :: "l"(p), "f"(s.x), "f"(s.y), "f"(s.z), "f"(s.w)
                 : "memory");
}

// flush: one REDG.128 for the run's raw sum; group leader also counts.
__device__ __forceinline__ void flush_seg(int seg, float4 s, int cnt, int sub) {
    red_add_v4(&g_sums4[seg * 8 + sub], s);
    if (sub == 0) atomicAdd(&g_counts[seg], (float)cnt);
}

// ---------------------------------------------------------------------------
// Kernel 1: gather + sorted-segment raw sum + counts (round-13 engine,
// VERBATIM — fastest measured configuration: 25.4 us).
// ---------------------------------------------------------------------------
__global__ void __launch_bounds__(256)
k_agg(const float* __restrict__ src,
      const int*   __restrict__ gidx,
      const int*   __restrict__ sid,
      int E)
{
    const int lane = threadIdx.x & 31;
    const int sub  = lane & 7;
    const long long warp  = ((long long)blockIdx.x * blockDim.x + threadIdx.x) >> 5;
    const long long start = warp * (long long)EPW;
    if (start >= E) return;

    if (start + EPW <= E) {
        // ---------- fast path: full 128-edge chunk ----------
        int4 gi4 = __ldg((const int4*)(gidx + start) + lane);
        int4 si4 = __ldg((const int4*)(sid  + start) + lane);
        int gi[4] = {gi4.x, gi4.y, gi4.z, gi4.w};
        int si[4] = {si4.x, si4.y, si4.z, si4.w};

        int    cur = -1, cnt = 0;
        float4 sum = make_float4(0.f, 0.f, 0.f, 0.f);

        #pragma unroll
        for (int jo = 0; jo < 32; jo += 8) {
            float4 val[8];
            #pragma unroll
            for (int jj = 0; jj < 8; ++jj) {
                const int j = jo + jj;
                int idx = __shfl_sync(FULL_MASK, gi[j & 3], j >> 2, 8);
                val[jj] = __ldg((const float4*)(src + (long long)idx * D) + sub);
            }
            #pragma unroll
            for (int jj = 0; jj < 8; ++jj) {
                const int j = jo + jj;
                int seg = __shfl_sync(FULL_MASK, si[j & 3], j >> 2, 8);
                if (seg != cur) {
                    if (cnt) flush_seg(cur, sum, cnt, sub);
                    cur = seg; sum = make_float4(0.f, 0.f, 0.f, 0.f); cnt = 0;
                }
                sum.x += val[jj].x; sum.y += val[jj].y;
                sum.z += val[jj].z; sum.w += val[jj].w;
                ++cnt;
            }
        }
        if (cnt) flush_seg(cur, sum, cnt, sub);
    } else {
        // ---------- tail path: partial chunk, per-group scalar loop ----------
        const int group = lane >> 3;
        long long gstart = start + (long long)group * 32;
        long long gend   = min(gstart + 32, (long long)E);

        int    cur = -1, cnt = 0;
        float4 sum = make_float4(0.f, 0.f, 0.f, 0.f);

        for (long long e = gstart; e < gend; ++e) {
            int idx = __ldg(gidx + e);
            int seg = __ldg(sid  + e);
            float4 v = __ldg((const float4*)(src + (long long)idx * D) + sub);
            if (seg != cur) {
                if (cnt) flush_seg(cur, sum, cnt, sub);
                cur = seg; sum = make_float4(0.f, 0.f, 0.f, 0.f); cnt = 0;
            }
            sum.x += v.x; sum.y += v.y; sum.z += v.z; sum.w += v.w;
            ++cnt;
        }
        if (cnt) flush_seg(cur, sum, cnt, sub);
    }
}

// ---------------------------------------------------------------------------
// Kernel 2: out = sums/max(cnt,1); restore scratch zeros. ILP-2 at full
// occupancy: thread t owns quads t and t+H (H = half). Both streams are
// coalesced; 2 independent L2-hot load chains per thread; out stores are
// full-line (no write-allocate reads).
// ---------------------------------------------------------------------------
__global__ void __launch_bounds__(256)
k_fin(float4* __restrict__ out4, int nq, int H)
{
    const int t = blockIdx.x * blockDim.x + threadIdx.x;
    if (t >= H) return;

    const int i0 = t;
    const int i1 = t + H;
    const bool has1 = (i1 < nq);

    // front-batch the independent loads
    float4 s0 = g_sums4[i0];
    float  c0 = g_counts[i0 >> 3];
    float4 s1;
    float  c1 = 1.0f;
    if (has1) { s1 = g_sums4[i1]; c1 = g_counts[i1 >> 3]; }

    {
        const float inv = 1.0f / fmaxf(c0, 1.0f);
        out4[i0] = make_float4(s0.x * inv, s0.y * inv, s0.z * inv, s0.w * inv);
        g_sums4[i0] = make_float4(0.f, 0.f, 0.f, 0.f);
        if ((i0 & 7) == 0) g_counts[i0 >> 3] = 0.0f;
    }
    if (has1) {
        const float inv = 1.0f / fmaxf(c1, 1.0f);
        out4[i1] = make_float4(s1.x * inv, s1.y * inv, s1.z * inv, s1.w * inv);
        g_sums4[i1] = make_float4(0.f, 0.f, 0.f, 0.f);
        if ((i1 & 7) == 0) g_counts[i1 >> 3] = 0.0f;
    }
}

// ---------------------------------------------------------------------------
extern "C" void kernel_launch(void* const* d_in, const int* in_sizes, int n_in,
                              void* d_out, int out_size)
{
    const float* src  = (const float*)d_in[0];   // [N, 32] f32
    const int*   gidx = (const int*)  d_in[1];   // [E] i32
    const int*   sid  = (const int*)  d_in[2];   // [E] i32 (sorted)
    float4*      out4 = (float4*)d_out;          // [N, 32] f32

    const int E  = in_sizes[1];
    const int nq = out_size / 4;

    // 1) gather + raw segment sums + counts into zeroed scratch
    {
        long long warps  = ((long long)E + EPW - 1) / EPW;
        long long tcount = warps * 32;
        int blocks = (int)((tcount + 255) / 256);
        k_agg<<<blocks, 256>>>(src, gidx, sid, E);
    }
    // 2) mean -> out, restore scratch zeros (ILP-2, full occupancy)
    {
        int H = (nq + 1) / 2;
        int blocks = (H + 255) / 256;
        k_fin<<<blocks, 256>>>(out4, nq, H);
    }
}